// round 8
// baseline (speedup 1.0000x reference)
#include <cuda_runtime.h>
#include <cstdint>

// Decoder_2430951489916 — v8: two kernels overlapped via PDL
// (programmatic dependent launch), NO global-atomic combine tail.
//   B=4, N=512, M=512, ZD=128, YD=2, XD=1
// out[b,m,y] = b_y + sum_n sum_c W[y,c]*z[b,n,c]*exp(-0.5*((x_m-t_n)*exp(-sigma_c))^2)
// Fast path (uniform sigma, true for bench):
//   out[b,m,y] = b_y + sum_n exp(coef*(x_m-t_n)^2) * zw[b,n,y],  zw = z @ W^T.
//
// K1: one warp per (b,n) row builds zw (float2 per row), 256x256.
// K2: one warp per (b,m) output point, 256x256, launched with
//     programmaticStreamSerialization: it starts WHILE K1 runs, does all
//     t/x/sigma-dependent work (16 exps/lane) pre-sync, then
//     cudaGridDependencySynchronize(), reads zw, 32 FMAs + warp reduce,
//     plain STG epilogue. This removes the 1.5us atomic-combine tail that
//     bounded rounds 5-7 and hides K1 under K2's prologue.

#define BB 4
#define NN 512
#define MM 512
#define ZDIM 128
#define YDIM 2

__device__ float2 g_zw[BB * NN];      // zw rows; rewritten every replay

// ---------------------------------------------------------------------------
// K1: zw[row] = (z[row]·W0, z[row]·W1), one warp per row (2048 warps).
// ---------------------------------------------------------------------------
__global__ __launch_bounds__(256) void prep_zw(const float* __restrict__ z,
                                               const float* __restrict__ W) {
    const int wid  = threadIdx.x >> 5;
    const int lane = threadIdx.x & 31;
    const int row  = blockIdx.x * 8 + wid;          // 0 .. B*N-1

    const float4 zv  = __ldg((const float4*)(z + (size_t)row * ZDIM) + lane);
    const float4 w0v = __ldg((const float4*)W + lane);
    const float4 w1v = __ldg((const float4*)W + 32 + lane);

    float a0 = zv.x * w0v.x;  a0 = fmaf(zv.y, w0v.y, a0);
    a0 = fmaf(zv.z, w0v.z, a0); a0 = fmaf(zv.w, w0v.w, a0);
    float a1 = zv.x * w1v.x;  a1 = fmaf(zv.y, w1v.y, a1);
    a1 = fmaf(zv.z, w1v.z, a1); a1 = fmaf(zv.w, w1v.w, a1);
#pragma unroll
    for (int o = 16; o; o >>= 1) {
        a0 += __shfl_xor_sync(0xFFFFFFFFu, a0, o);
        a1 += __shfl_xor_sync(0xFFFFFFFFu, a1, o);
    }
    if (lane == 0) g_zw[row] = make_float2(a0, a1);
    // implicit PDL completion trigger at kernel end -> zw globally visible
    // to K2 after its cudaGridDependencySynchronize().
}

// ---------------------------------------------------------------------------
// K2: one warp per (b,m). Pre-sync: exps from t/x. Post-sync: zw FMAs + STG.
// ---------------------------------------------------------------------------
__global__ __launch_bounds__(256) void decoder_main(
    const float* __restrict__ t,
    const float* __restrict__ z,
    const float* __restrict__ x,
    const float* __restrict__ sigma,
    const float* __restrict__ W,
    const float* __restrict__ bias,
    float* __restrict__ out) {
    const int tid   = threadIdx.x;
    const int wid   = tid >> 5;                      // 8 warps -> 8 m-points
    const int lane  = tid & 31;
    const int b     = blockIdx.x / (MM / 8);
    const int mtile = blockIdx.x % (MM / 8);
    const int m     = mtile * 8 + wid;

    // ---- pre-sync work: depends only on t, x, sigma, bias ----
    const float xm = __ldg(x + b * MM + m);          // XD == 1 (warp broadcast)
    const float b0 = __ldg(bias + 0);
    const float b1 = __ldg(bias + 1);
    const float s0 = __ldg(sigma);
    const float coef = -0.5f * __expf(-2.0f * s0);

    const float* tg = t + b * NN;
    float e[16];
#pragma unroll
    for (int k = 0; k < 16; ++k) {
        const float d = xm - __ldg(tg + k * 32 + lane);
        e[k] = __expf(coef * d * d);
    }

    const int nonuniform =
        __syncthreads_or((tid < ZDIM) && (__ldg(sigma + tid) != s0));

    // ---- wait for K1's zw (no-op if launched without PDL) ----
    cudaGridDependencySynchronize();

    float s_0, s_1;
    if (!nonuniform) {
        const float2* zwr = g_zw + b * NN;
        float p0 = 0.f, q0 = 0.f, p1 = 0.f, q1 = 0.f;
#pragma unroll
        for (int k = 0; k < 16; k += 2) {
            const float2 wa = zwr[k * 32 + lane];          // coalesced LDG.64
            const float2 wb = zwr[(k + 1) * 32 + lane];
            p0 = fmaf(e[k],     wa.x, p0);
            p1 = fmaf(e[k],     wa.y, p1);
            q0 = fmaf(e[k + 1], wb.x, q0);
            q1 = fmaf(e[k + 1], wb.y, q1);
        }
        s_0 = p0 + q0;
        s_1 = p1 + q1;
    } else {
        // general path: per-channel length scales (correct for any sigma)
        s_0 = 0.f; s_1 = 0.f;
        for (int n = 0; n < NN; ++n) {
            const float d  = xm - __ldg(tg + n);
            const float d2 = d * d;
            const float* zr = z + (size_t)(b * NN + n) * ZDIM;
#pragma unroll
            for (int j = 0; j < ZDIM / 32; ++j) {
                const int   c   = lane + 32 * j;
                const float inv = __expf(-__ldg(sigma + c));
                const float qq  = -0.5f * inv * inv;
                const float ev  = __ldg(zr + c) * __expf(qq * d2);
                s_0 = fmaf(ev, __ldg(W + c),        s_0);
                s_1 = fmaf(ev, __ldg(W + ZDIM + c), s_1);
            }
        }
    }

    // ---- warp reduce + plain store (no atomics) ----
#pragma unroll
    for (int o = 16; o; o >>= 1) {
        s_0 += __shfl_xor_sync(0xFFFFFFFFu, s_0, o);
        s_1 += __shfl_xor_sync(0xFFFFFFFFu, s_1, o);
    }
    if (lane == 0) {
        float2* op = (float2*)(out + (size_t)(b * MM + m) * YDIM);
        *op = make_float2(s_0 + b0, s_1 + b1);
    }
}

// ---------------------------------------------------------------------------
extern "C" void kernel_launch(void* const* d_in, const int* in_sizes, int n_in,
                              void* d_out, int out_size) {
    const float* t     = (const float*)d_in[0];
    const float* z     = (const float*)d_in[1];
    const float* x     = (const float*)d_in[2];
    const float* sigma = (const float*)d_in[3];
    const float* W     = (const float*)d_in[4];
    const float* bias  = (const float*)d_in[5];
    float* out = (float*)d_out;

    // K1: plain launch on the (captured) default stream.
    prep_zw<<<BB * NN / 8, 256>>>(z, W);

    // K2: PDL — allowed to begin while K1 runs; gridsync gates zw reads.
    cudaLaunchConfig_t cfg = {};
    cfg.gridDim  = dim3(BB * (MM / 8), 1, 1);
    cfg.blockDim = dim3(256, 1, 1);
    cfg.dynamicSmemBytes = 0;
    cfg.stream = 0;  // legacy default stream (same one the harness captures)
    cudaLaunchAttribute attr[1];
    attr[0].id = cudaLaunchAttributeProgrammaticStreamSerialization;
    attr[0].val.programmaticStreamSerializationAllowed = 1;
    cfg.attrs = attr;
    cfg.numAttrs = 1;
    cudaLaunchKernelEx(&cfg, decoder_main, t, z, x, sigma, W, bias, out);
}

// round 9
// speedup vs baseline: 1.0295x; 1.0295x over previous
#include <cuda_runtime.h>
#include <cstdint>

// Decoder_2430951489916 — v9: ONE kernel, cluster/DSMEM zw broadcast,
// zero global atomics, plain-store epilogue.
//   B=4, N=512, M=512, ZD=128, YD=2, XD=1
// out[b,m,y] = b_y + sum_n sum_c W[y,c]*z[b,n,c]*exp(-0.5*((x_m-t_n)*exp(-sigma_c))^2)
// Fast path (uniform sigma, true for bench):
//   out[b,m,y] = b_y + sum_n exp(coef*(x_m-t_n)^2) * zw[b,n,y],  zw = z @ W^T.
//
// R8 lesson: every kernel pays a ~5us ramp -> must be ONE kernel; R5-R7
// lesson: the global-atomic combine tail costs ~1us over a plain-store body.
// Here 16 clusters x 8 CTAs: each CTA builds zw for its 64 n-rows (z read
// once, coalesced) and broadcasts each row's float2 to all 8 cluster CTAs
// via mapa + st.shared::cluster (lanes 0-7 hit the 8 peers in parallel).
// One cluster barrier, then each warp finishes one m-point from LOCAL smem
// and does a plain STG.64. Exps overlap the z loads as before.

#define BB 4
#define NN 512
#define MM 512
#define ZDIM 128
#define YDIM 2
#define CLUSTER 8
#define NTHREADS 512
#define GRID (BB * 4 * CLUSTER)      // 128 CTAs = 16 clusters

typedef unsigned long long u64;

__device__ __forceinline__ uint32_t smem_u32(const void* p) {
    uint32_t a;
    asm("{ .reg .u64 tt; cvta.to.shared.u64 tt, %1; cvt.u32.u64 %0, tt; }"
        : "=r"(a) : "l"(p));
    return a;
}
// store float2 into CTA `rank`'s smem at this CTA-relative address
__device__ __forceinline__ void st_cluster_f2(uint32_t addr, uint32_t rank,
                                              float a, float b) {
    u64 v; asm("mov.b64 %0,{%1,%2};" : "=l"(v) : "f"(a), "f"(b));
    uint32_t r;
    asm("mapa.shared::cluster.u32 %0, %1, %2;" : "=r"(r) : "r"(addr), "r"(rank));
    asm volatile("st.shared::cluster.b64 [%0], %1;" :: "r"(r), "l"(v) : "memory");
}

__global__ void __launch_bounds__(NTHREADS) decoder_v9(
    const float* __restrict__ t,
    const float* __restrict__ z,
    const float* __restrict__ x,
    const float* __restrict__ sigma,
    const float* __restrict__ W,
    const float* __restrict__ bias,
    float* __restrict__ out) {
    __shared__ float2 zw_s[NN];      // full zw for this batch (peer-filled)

    const int tid  = threadIdx.x;
    const int w    = tid >> 5;       // 16 warps
    const int lane = tid & 31;
    uint32_t rank;
    asm("mov.u32 %0, %%cluster_ctarank;" : "=r"(rank));
    const int cl = blockIdx.x / CLUSTER;     // cluster id (ranks are consecutive)
    const int b  = cl >> 2;                  // batch
    const int mq = cl & 3;                   // m-quarter
    const int m  = mq * 128 + (int)rank * 16 + w;   // this warp's output point

    // ---- issue all long-latency loads up front ----
    const float  xm  = __ldg(x + b * MM + m);        // XD == 1, warp-uniform
    const float  b0  = __ldg(bias + 0);
    const float  b1  = __ldg(bias + 1);
    const float  s0  = __ldg(sigma);
    const float4 w0v = __ldg((const float4*)W + lane);
    const float4 w1v = __ldg((const float4*)W + 32 + lane);
    const int nbase = (int)rank * 64 + w * 4;        // this warp's 4 z rows
    float4 zv[4];
#pragma unroll
    for (int j = 0; j < 4; ++j)
        zv[j] = __ldg((const float4*)(z + (size_t)(b * NN + nbase + j) * ZDIM) + lane);

    // ---- exps overlap the z loads (depend only on t, x, sigma) ----
    const float coef = -0.5f * __expf(-2.0f * s0);
    const float* tg  = t + b * NN;
    float e[16];
#pragma unroll
    for (int k = 0; k < 16; ++k) {
        const float d = xm - __ldg(tg + 32 * k + lane);
        e[k] = __expf(coef * d * d);
    }

    // CTA-local sigma-uniformity vote (same verdict in every CTA)
    const int nonuniform =
        __syncthreads_or((tid < ZDIM) && (__ldg(sigma + tid) != s0));

    // ---- zw rows: dot + full shuffle reduce, broadcast to all 8 CTAs ----
    const uint32_t zw_base = smem_u32(zw_s);
#pragma unroll
    for (int j = 0; j < 4; ++j) {
        float a0 = zv[j].x * w0v.x;  a0 = fmaf(zv[j].y, w0v.y, a0);
        a0 = fmaf(zv[j].z, w0v.z, a0); a0 = fmaf(zv[j].w, w0v.w, a0);
        float a1 = zv[j].x * w1v.x;  a1 = fmaf(zv[j].y, w1v.y, a1);
        a1 = fmaf(zv[j].z, w1v.z, a1); a1 = fmaf(zv[j].w, w1v.w, a1);
#pragma unroll
        for (int o = 16; o; o >>= 1) {
            a0 += __shfl_xor_sync(0xFFFFFFFFu, a0, o);
            a1 += __shfl_xor_sync(0xFFFFFFFFu, a1, o);
        }
        // all lanes hold the sums; lanes 0..7 write to the 8 cluster CTAs
        if (lane < CLUSTER)
            st_cluster_f2(zw_base + (uint32_t)(nbase + j) * 8u, (uint32_t)lane, a0, a1);
    }

    // ---- cluster barrier: arrive(release) orders DSMEM stores; wait(acquire) ----
    asm volatile("barrier.cluster.arrive.aligned;" ::: "memory");
    asm volatile("barrier.cluster.wait.aligned;"  ::: "memory");

    float s_0, s_1;
    if (!nonuniform) {
        float p0 = 0.f, q0 = 0.f, p1 = 0.f, q1 = 0.f;
#pragma unroll
        for (int k = 0; k < 16; k += 2) {
            const float2 wa = zw_s[32 * k + lane];
            const float2 wb = zw_s[32 * (k + 1) + lane];
            p0 = fmaf(e[k],     wa.x, p0);  p1 = fmaf(e[k],     wa.y, p1);
            q0 = fmaf(e[k + 1], wb.x, q0);  q1 = fmaf(e[k + 1], wb.y, q1);
        }
        s_0 = p0 + q0;
        s_1 = p1 + q1;
    } else {
        // general path: per-channel length scales (correct for any sigma)
        s_0 = 0.f; s_1 = 0.f;
        float qv[4], wc0[4], wc1[4];
#pragma unroll
        for (int j = 0; j < 4; ++j) {
            const int c = lane + 32 * j;
            const float inv = __expf(-__ldg(sigma + c));
            qv[j]  = -0.5f * inv * inv;
            wc0[j] = __ldg(W + c);
            wc1[j] = __ldg(W + ZDIM + c);
        }
        for (int n = 0; n < NN; ++n) {
            const float d  = xm - __ldg(tg + n);
            const float d2 = d * d;
            const float* zr = z + (size_t)(b * NN + n) * ZDIM;
#pragma unroll
            for (int j = 0; j < 4; ++j) {
                const float ev = __ldg(zr + lane + 32 * j) * __expf(qv[j] * d2);
                s_0 = fmaf(ev, wc0[j], s_0);
                s_1 = fmaf(ev, wc1[j], s_1);
            }
        }
    }

    // ---- warp reduce + plain store (no atomics anywhere) ----
#pragma unroll
    for (int o = 16; o; o >>= 1) {
        s_0 += __shfl_xor_sync(0xFFFFFFFFu, s_0, o);
        s_1 += __shfl_xor_sync(0xFFFFFFFFu, s_1, o);
    }
    if (lane == 0)
        *(float2*)(out + 2 * (size_t)(b * MM + m)) = make_float2(s_0 + b0, s_1 + b1);
}

// ---------------------------------------------------------------------------
extern "C" void kernel_launch(void* const* d_in, const int* in_sizes, int n_in,
                              void* d_out, int out_size) {
    const float* t     = (const float*)d_in[0];
    const float* z     = (const float*)d_in[1];
    const float* x     = (const float*)d_in[2];
    const float* sigma = (const float*)d_in[3];
    const float* W     = (const float*)d_in[4];
    const float* bias  = (const float*)d_in[5];
    float* out = (float*)d_out;

    cudaLaunchConfig_t cfg = {};
    cfg.gridDim  = dim3(GRID, 1, 1);
    cfg.blockDim = dim3(NTHREADS, 1, 1);
    cfg.dynamicSmemBytes = 0;
    cfg.stream = 0;                          // captured default stream
    cudaLaunchAttribute attr[1];
    attr[0].id = cudaLaunchAttributeClusterDimension;
    attr[0].val.clusterDim.x = CLUSTER;
    attr[0].val.clusterDim.y = 1;
    attr[0].val.clusterDim.z = 1;
    cfg.attrs = attr;
    cfg.numAttrs = 1;
    cudaLaunchKernelEx(&cfg, decoder_v9, t, z, x, sigma, W, bias, out);
}